// round 17
// baseline (speedup 1.0000x reference)
#include <cuda_runtime.h>
#include <cuda_fp16.h>
#include <stdint.h>

// out[m] = x[m]·W + b + 0.5*||x[m]V||^2 - 0.5*(sum_i x[m,i])^2 * ||V.sum(0)||^2
// x: (16384,4096) f32, W: (1,4096) f32, b: (1,) f32, V: (4096,128) f32, out f32.
// GEMM fp16 (V pre-scaled 4096), f16 acc; side sums exact fp32.
// SPLIT-K grid 294 (147 row-blocks x 2 K-halves), 2 CTAs/SM.
// Warp layout 2 m-halves x 4 n-quads (L1TEX-optimal for 128-reg budget).
// COMBINE FUSED: second-finishing CTA of each rb pair reduces its rows
// (atomic flag, fence-protected, self-resetting for graph replay).

#define MROWS 16384
#define KDIM  4096
#define NDIM  128
#define KC    64
#define NCHH  32                   // chunks per K-half
#define CTAROWS 112
#define NRB   147
#define GRID  (NRB * 2)
#define AROW  144                  // padded smem row stride (bytes)
#define ABUF  (CTAROWS * AROW)     // 16128
#define BBUF  (128 * AROW)         // 18432
#define SMEM_TOTAL (2 * ABUF + 2 * BBUF)   // 69120 -> 2 CTAs = 138240 < 227KB

#define VSCALE 4096.0f
#define T1SCALE (0.5f / (VSCALE * VSCALE))

__device__ __half g_Vt[(size_t)64 * NDIM * KC];    // chunk-major [c][n][kk], fp16 of 4096*V^T
__device__ float g_spart[256 * NDIM];
__device__ float g_sp2[16 * NDIM];
__device__ float g_s2;
__device__ uint32_t g_xv[2][(size_t)MROWS * 64];   // f16x2 col-pairs, per K-half
__device__ float g_sxp[2][MROWS];
__device__ float g_swp[2][MROWS];
__device__ int g_flag[NRB];                        // pair-completion flags (self-reset)

// ---------------- helpers ----------------

static __device__ __forceinline__ uint32_t smem_u32(const void* p) {
    uint32_t r;
    asm("{ .reg .u64 t; cvta.to.shared.u64 t, %1; cvt.u32.u64 %0, t; }"
        : "=r"(r) : "l"(p));
    return r;
}

static __device__ __forceinline__ uint32_t pack2h(float lo, float hi) {
    __half2 h = __floats2half2_rn(lo, hi);
    return *reinterpret_cast<uint32_t*>(&h);
}

#define MMA_F16(d0, d1, a0, a1, a2, a3, b0, b1)                            \
    asm volatile(                                                          \
        "mma.sync.aligned.m16n8k16.row.col.f16.f16.f16.f16 "               \
        "{%0,%1}, {%2,%3,%4,%5}, {%6,%7}, {%0,%1};"                        \
        : "+r"(d0), "+r"(d1)                                               \
        : "r"(a0), "r"(a1), "r"(a2), "r"(a3), "r"(b0), "r"(b1))

#define LDSM_X4(r0, r1, r2, r3, addr)                                      \
    asm volatile("ldmatrix.sync.aligned.m8n8.x4.shared.b16 "               \
                 "{%0,%1,%2,%3}, [%4];"                                    \
                 : "=r"(r0), "=r"(r1), "=r"(r2), "=r"(r3) : "r"(addr))

// ---------------- prep kernels ----------------

// 256 blocks; block b handles 16 K-rows [16b,16b+16) with float4 loads.
__global__ void prep_kernel(const float* __restrict__ V) {
    __shared__ __align__(16) float smf[16 * 132];   // 132-float row stride
    __shared__ float ps[256];
    const int t = threadIdx.x;
    const int b = blockIdx.x;

    // phase 1: vectorized load (V row = 32 contiguous float4)
    const float4* V4 = (const float4*)V;
#pragma unroll
    for (int j = 0; j < 2; j++) {
        const int idx = t + 256 * j;
        const int k = idx >> 5, c4 = idx & 31;
        const float4 f = V4[(size_t)b * 512 + idx];
        *(float4*)&smf[k * 132 + c4 * 4] = f;
    }
    __syncthreads();

    // phase 2: partial column sums (k split across 2 groups of 8)
    const int n = t & 127, g = t >> 7;
    float partial = 0.f;
#pragma unroll
    for (int k = 0; k < 8; k++) partial += smf[(g * 8 + k) * 132 + n];
    ps[t] = partial;
    __syncthreads();
    if (t < 128) g_spart[b * 128 + t] = ps[t] + ps[t + 128];

    // phase 3: convert + transpose out: thread handles 8 k of row n (16B)
    {
        uint32_t u[4];
#pragma unroll
        for (int i = 0; i < 4; i++) {
            const float v0 = smf[(g * 8 + 2 * i) * 132 + n] * VSCALE;
            const float v1 = smf[(g * 8 + 2 * i + 1) * 132 + n] * VSCALE;
            u[i] = pack2h(v0, v1);
        }
        uint4* dst = (uint4*)((char*)g_Vt + (size_t)(b >> 2) * 16384 + n * 128
                              + (b & 3) * 32 + g * 16);
        dst[0] = make_uint4(u[0], u[1], u[2], u[3]);
    }
}

__global__ void s2a_kernel() {
    __shared__ float sh[256];
    const int t = threadIdx.x;
    const int n = t & 127, part = t >> 7;
    const int b0 = blockIdx.x * 16 + part * 8;
    float s = 0.f;
#pragma unroll
    for (int j = 0; j < 8; j++) s += g_spart[(b0 + j) * 128 + n];
    sh[t] = s;
    __syncthreads();
    if (t < 128) g_sp2[blockIdx.x * 128 + t] = sh[t] + sh[t + 128];
}

__global__ void s2b_kernel() {
    __shared__ float sq[128];
    const int t = threadIdx.x;
    float s = 0.f;
#pragma unroll
    for (int j = 0; j < 16; j++) s += g_sp2[j * 128 + t];
    sq[t] = s * s;
    __syncthreads();
    for (int o = 64; o > 0; o >>= 1) {
        if (t < o) sq[t] += sq[t + o];
        __syncthreads();
    }
    if (t == 0) g_s2 = sq[0];
}

// ---------------- main kernel (split-K half + fused combine) ----------------

__global__ void __launch_bounds__(256, 2) fm_main(
    const float* __restrict__ x, const float* __restrict__ W,
    const float* __restrict__ bias, float* __restrict__ out)
{
    extern __shared__ __align__(16) char smem[];

    const int t = threadIdx.x;
    const int wid = t >> 5, lane = t & 31;
    const int nq = wid & 3;
    const int mh = wid >> 2;
    const int rb = blockIdx.x >> 1;
    const int kh = blockIdx.x & 1;
    int mbase = rb * CTAROWS;
    if (mbase > MROWS - CTAROWS) mbase = MROWS - CTAROWS;  // overlap; dup writes identical

    const uint32_t sAu = smem_u32(smem);
    const uint32_t sBu = sAu + 2 * ABUF;

    const char* xb = (const char*)x + ((size_t)(mbase + (t >> 4)) << 14)
                   + (size_t)kh * 8192 + (t & 15) * 16;
    const char* vb = (const char*)g_Vt + (size_t)kh * NCHH * 16384 + (size_t)t * 16;
    const float4* wp = (const float4*)W + kh * 512 + (t & 15);

    const uint32_t asts = sAu + (t >> 4) * AROW + (t & 15) * 8;
    const uint32_t bsts = sBu + (t >> 3) * AROW + (t & 7) * 16;

    const uint32_t alds = sAu + (uint32_t)(mh * 64 + (lane & 15)) * AROW
                        + (lane >> 4) * 16;
    const uint32_t blds = sBu + (uint32_t)(nq * 32 + (lane >> 4) * 8 + (lane & 7)) * AROW
                        + ((lane >> 3) & 1) * 16;

    uint32_t acc[4][4][2];
#pragma unroll
    for (int s = 0; s < 4; s++)
#pragma unroll
        for (int j = 0; j < 4; j++) { acc[s][j][0] = 0u; acc[s][j][1] = 0u; }

    float sx[7], sw[7];
#pragma unroll
    for (int i = 0; i < 7; i++) { sx[i] = 0.f; sw[i] = 0.f; }

    float4 areg[7];
    uint4  breg[4];

#define LOADA(c) do {                                                       \
        _Pragma("unroll")                                                   \
        for (int i = 0; i < 7; i++)                                         \
            areg[i] = *(const float4*)(xb + ((size_t)i << 18) + (c) * 256); \
    } while (0)

#define LOADB(c) do {                                                       \
        _Pragma("unroll")                                                   \
        for (int j = 0; j < 4; j++)                                         \
            breg[j] = *(const uint4*)(vb + (size_t)(c) * 16384 + j * 4096); \
    } while (0)

#define SUMS_STS(c, buf) do {                                               \
        const float4 w4 = wp[(c) * 16];                                     \
        const uint32_t aof_ = (uint32_t)(buf) * ABUF;                       \
        const uint32_t bof_ = (uint32_t)(buf) * BBUF;                       \
        _Pragma("unroll")                                                   \
        for (int i = 0; i < 7; i++) {                                       \
            const float4 q = areg[i];                                       \
            sx[i] += (q.x + q.y) + (q.z + q.w);                             \
            sw[i] += q.x * w4.x + q.y * w4.y + q.z * w4.z + q.w * w4.w;     \
            const uint32_t p0 = pack2h(q.x, q.y), p1 = pack2h(q.z, q.w);    \
            asm volatile("st.shared.v2.b32 [%0], {%1,%2};"                  \
                         :: "r"(asts + aof_ + i * (16 * AROW)), "r"(p0), "r"(p1)); \
        }                                                                   \
        _Pragma("unroll")                                                   \
        for (int j = 0; j < 4; j++)                                         \
            asm volatile("st.shared.v4.b32 [%0], {%1,%2,%3,%4};"            \
                         :: "r"(bsts + bof_ + j * (32 * AROW)), "r"(breg[j].x), \
                            "r"(breg[j].y), "r"(breg[j].z), "r"(breg[j].w));\
    } while (0)

#define MMA_CHUNK(NST, aof, bof) do {                                       \
        _Pragma("unroll")                                                   \
        for (int ks = 0; ks < 4; ks++) {                                    \
            uint32_t bfr[8];                                                \
            LDSM_X4(bfr[0], bfr[1], bfr[2], bfr[3],                         \
                    blds + (bof) + ks * 32);                                \
            LDSM_X4(bfr[4], bfr[5], bfr[6], bfr[7],                         \
                    blds + (bof) + ks * 32 + 16 * AROW);                    \
            uint32_t afr[NST][4];                                           \
            _Pragma("unroll")                                               \
            for (int s = 0; s < NST; s++)                                   \
                LDSM_X4(afr[s][0], afr[s][1], afr[s][2], afr[s][3],         \
                        alds + (aof) + ks * 32 + s * (16 * AROW));          \
            _Pragma("unroll")                                               \
            for (int s = 0; s < NST; s++)                                   \
                _Pragma("unroll")                                           \
                for (int nt = 0; nt < 4; nt++)                              \
                    MMA_F16(acc[s][nt][0], acc[s][nt][1],                   \
                            afr[s][0], afr[s][1], afr[s][2], afr[s][3],     \
                            bfr[nt * 2], bfr[nt * 2 + 1]);                  \
        }                                                                   \
    } while (0)

    LOADA(0); LOADB(0);
    SUMS_STS(0, 0);
    __syncthreads();

#pragma unroll 1
    for (int c = 0; c < NCHH; c++) {
        const bool more = (c + 1 < NCHH);
        if (more) { LOADA(c + 1); LOADB(c + 1); }

        const uint32_t aof = (uint32_t)(c & 1) * ABUF;
        const uint32_t bof = (uint32_t)(c & 1) * BBUF;

        if (mh == 0) MMA_CHUNK(4, aof, bof);
        else         MMA_CHUNK(3, aof, bof);

        if (more) SUMS_STS(c + 1, (c + 1) & 1);
        __syncthreads();
    }

    // ---------------- epilogue: store f16 partials to slab ----------------
    {
        uint32_t* slab = g_xv[kh];
        const int nst = mh ? 3 : 4;
#pragma unroll
        for (int s = 0; s < 4; s++) {
            if (s >= nst) break;
            const int r0 = mbase + (mh * 4 + s) * 16 + (lane >> 2);
#pragma unroll
            for (int nt = 0; nt < 4; nt++) {
                const int cp = nq * 16 + nt * 4 + (lane & 3);
                slab[(size_t)r0 * 64 + cp]       = acc[s][nt][0];
                slab[(size_t)(r0 + 8) * 64 + cp] = acc[s][nt][1];
            }
        }
    }

    // side sums
#pragma unroll
    for (int i = 0; i < 7; i++) {
#pragma unroll
        for (int o = 8; o > 0; o >>= 1) {
            sx[i] += __shfl_xor_sync(0xffffffffu, sx[i], o);
            sw[i] += __shfl_xor_sync(0xffffffffu, sw[i], o);
        }
    }
    if ((t & 15) == 0) {
        const int h = t >> 4;
#pragma unroll
        for (int i = 0; i < 7; i++) {
            const int row = mbase + i * 16 + h;
            g_sxp[kh][row] = sx[i];
            g_swp[kh][row] = sw[i];
        }
    }

    // ---------------- fused combine: second finisher of the rb pair ----------------
    __syncthreads();
    int* sflag = (int*)smem;   // smem buffers dead now
    if (t == 0) {
        __threadfence();                       // release our slab/side writes
        sflag[0] = atomicAdd(&g_flag[rb], 1);
    }
    __syncthreads();
    if (sflag[0] == 1) {
        if (t == 0) g_flag[rb] = 0;            // self-reset for next graph replay
        __threadfence();                       // acquire partner's writes
        const float s2v = g_s2;
        const float bb = bias[0];
        for (int rr = wid; rr < CTAROWS; rr += 8) {
            const int m = mbase + rr;
            const uint2 a = ((const uint2*)g_xv[0])[(size_t)m * 32 + lane];
            const uint2 b2 = ((const uint2*)g_xv[1])[(size_t)m * 32 + lane];
            const float2 a0 = __half22float2(*reinterpret_cast<const __half2*>(&a.x));
            const float2 a1 = __half22float2(*reinterpret_cast<const __half2*>(&a.y));
            const float2 b0 = __half22float2(*reinterpret_cast<const __half2*>(&b2.x));
            const float2 b1 = __half22float2(*reinterpret_cast<const __half2*>(&b2.y));
            const float u0 = a0.x + b0.x, v0 = a0.y + b0.y;
            const float u1 = a1.x + b1.x, v1 = a1.y + b1.y;
            float accv = u0 * u0 + v0 * v0 + u1 * u1 + v1 * v1;
#pragma unroll
            for (int o = 16; o > 0; o >>= 1)
                accv += __shfl_xor_sync(0xffffffffu, accv, o);
            if (lane == 0) {
                const float sxv = g_sxp[0][m] + g_sxp[1][m];
                const float swv = g_swp[0][m] + g_swp[1][m];
                out[m] = swv + bb + T1SCALE * accv - 0.5f * sxv * sxv * s2v;
            }
        }
    }
}

// ---------------- launch ----------------

extern "C" void kernel_launch(void* const* d_in, const int* in_sizes, int n_in,
                              void* d_out, int out_size) {
    (void)in_sizes; (void)n_in; (void)out_size;
    const float* x = (const float*)d_in[0];
    const float* W = (const float*)d_in[1];
    const float* b = (const float*)d_in[2];
    const float* V = (const float*)d_in[3];
    float* out = (float*)d_out;

    cudaFuncSetAttribute(fm_main, cudaFuncAttributeMaxDynamicSharedMemorySize, SMEM_TOTAL);

    prep_kernel<<<256, 256>>>(V);
    s2a_kernel<<<16, 256>>>();
    s2b_kernel<<<1, 128>>>();
    fm_main<<<GRID, 256, SMEM_TOTAL>>>(x, W, b, out);
}